// round 13
// baseline (speedup 1.0000x reference)
#include <cuda_runtime.h>
#include <cuda_bf16.h>
#include <cstdint>

#define BATCH 128
#define NH    8
#define NT    256
#define HDIM  64
#define MODEL 512
#define NBH   (BATCH*NH)    // 1024
#define MTOT  (BATCH*NT)    // 32768
#define QKVN  (3*NH*HDIM)   // 1536
#define KX    1536          // extended K = 3*512

// ---------------- scratch (static __device__, no runtime allocation) -------
__device__ float g_v[(size_t)NBH*NT*HDIM];
__device__ float g_S[(size_t)NBH*NT*NT];
__device__ __nv_bfloat16 g_qe[(size_t)NBH*NT*128];   // [qh|ql] per row (scaled)
__device__ __nv_bfloat16 g_ke[(size_t)NBH*NT*128];   // [kh|kl] per row
__device__ __nv_bfloat16 g_vt[(size_t)NBH*64*512];   // [Vh|Vl], V transposed
__device__ __nv_bfloat16 g_xs[(size_t)MTOT*KX];      // [Ah|Al|Ah] of x
__device__ __nv_bfloat16 g_qws[(size_t)QKVN*KX];     // [Bh|Bh|Bl] of qkv_w
__device__ __nv_bfloat16 g_pws[(size_t)MODEL*KX];    // [Bh|Bh|Bl] of proj_w
__device__ __nv_bfloat16 g_ohs[(size_t)MTOT*KX];     // [Ah|Al|Ah] of attn out

// ---------------- helpers ---------------------------------------------------
__device__ __forceinline__ uint32_t smem_u32(const void* p) {
    uint32_t a;
    asm("{ .reg .u64 t; cvta.to.shared.u64 t, %1; cvt.u32.u64 %0, t; }"
        : "=r"(a) : "l"(p));
    return a;
}
__device__ __forceinline__ void cp16(uint32_t s, const void* g) {
    asm volatile("cp.async.cg.shared.global [%0], [%1], 16;" :: "r"(s), "l"(g));
}
#define CP_COMMIT() asm volatile("cp.async.commit_group;")
#define CP_WAIT0()  asm volatile("cp.async.wait_group 0;")
#define CP_WAIT1()  asm volatile("cp.async.wait_group 1;")
__device__ __forceinline__ void ldm4(uint32_t& r0, uint32_t& r1, uint32_t& r2,
                                     uint32_t& r3, uint32_t a) {
    asm volatile("ldmatrix.sync.aligned.m8n8.x4.shared.b16 {%0,%1,%2,%3}, [%4];"
                 : "=r"(r0), "=r"(r1), "=r"(r2), "=r"(r3) : "r"(a));
}
__device__ __forceinline__ void mma16816(float* c, const uint32_t* a,
                                         uint32_t b0, uint32_t b1) {
    asm volatile(
        "mma.sync.aligned.m16n8k16.row.col.f32.bf16.bf16.f32 "
        "{%0,%1,%2,%3}, {%4,%5,%6,%7}, {%8,%9}, {%0,%1,%2,%3};"
        : "+f"(c[0]), "+f"(c[1]), "+f"(c[2]), "+f"(c[3])
        : "r"(a[0]), "r"(a[1]), "r"(a[2]), "r"(a[3]), "r"(b0), "r"(b1));
}
__device__ __forceinline__ void split1(float v, __nv_bfloat16& h, __nv_bfloat16& l) {
    h = __float2bfloat16(v);
    l = __float2bfloat16(v - __bfloat162float(h));
}

// ---------------- split kernels (vectorized x2) -----------------------------
__global__ void split_a_kernel(const float* __restrict__ s, __nv_bfloat16* d,
                               int totpairs) {
    int i = blockIdx.x * 256 + threadIdx.x;
    if (i >= totpairs) return;
    int r = i >> 8, kp = i & 255;          // 256 pairs per 512-row
    float2 v = ((const float2*)s)[i];
    __nv_bfloat16 h0, l0, h1, l1;
    split1(v.x, h0, l0); split1(v.y, h1, l1);
    __nv_bfloat162 th, tl; th.x = h0; th.y = h1; tl.x = l0; tl.y = l1;
    __nv_bfloat162* base = (__nv_bfloat162*)(d + (size_t)r * KX) + kp;
    base[0] = th; base[256] = tl; base[512] = th;
}
__global__ void split_b_kernel(const float* __restrict__ s, __nv_bfloat16* d,
                               int totpairs) {
    int i = blockIdx.x * 256 + threadIdx.x;
    if (i >= totpairs) return;
    int r = i >> 8, kp = i & 255;
    float2 v = ((const float2*)s)[i];
    __nv_bfloat16 h0, l0, h1, l1;
    split1(v.x, h0, l0); split1(v.y, h1, l1);
    __nv_bfloat162 th, tl; th.x = h0; th.y = h1; tl.x = l0; tl.y = l1;
    __nv_bfloat162* base = (__nv_bfloat162*)(d + (size_t)r * KX) + kp;
    base[0] = th; base[256] = th; base[512] = tl;
}

// ---------------- bf16 mma.sync GEMM (large, dense) -------------------------
// BM=128 BN=128 BK=64, 256 threads, warp tile 32x64, 3 stages, 2 CTAs/SM.
#define BM 128
#define BN 128
#define BK 64
#define NSTG 3
#define ROWB 144u                         // padded row: 72 bf16 = 144B
#define STGB (2u * BM * ROWB)             // 36864B
#define GSMEM (NSTG * STGB)               // 110592B

template<int MODE>
__global__ __launch_bounds__(256, 2) void gemm_mma(
    const __nv_bfloat16* __restrict__ gA, const __nv_bfloat16* __restrict__ gB,
    const float* __restrict__ bias, float* __restrict__ outp)
{
    extern __shared__ char smem[];
    const uint32_t sb = smem_u32(smem);
    const int tid = threadIdx.x, wid = tid >> 5, lane = tid & 31;
    const int m0 = blockIdx.y * BM;
    const int n0 = blockIdx.x * BN;
    const int warp_m = (wid & 3) * 32;
    const int warp_n = (wid >> 2) * 64;

    auto load_stage = [&](int ks, int buf) {
        const size_t kofs = (size_t)ks * BK;
        const uint32_t abase = sb + buf * STGB;
        const uint32_t bbase = abase + BM * ROWB;
        #pragma unroll
        for (int t = 0; t < 8; t++) {
            const int idx = tid + t * 256;
            if (idx < 1024) {           // A: 128 rows x 8 chunks
                const int r = idx >> 3, c = (idx & 7) * 8;
                cp16(abase + r * ROWB + c * 2, gA + (size_t)(m0 + r) * KX + kofs + c);
            } else {                    // B: 128 rows x 8 chunks
                const int j = idx - 1024;
                const int r = j >> 3, c = (j & 7) * 8;
                cp16(bbase + r * ROWB + c * 2, gB + (size_t)(n0 + r) * KX + kofs + c);
            }
        }
    };

    const int NK = KX / BK;   // 24
    load_stage(0, 0); CP_COMMIT();
    load_stage(1, 1); CP_COMMIT();

    float acc[2][8][4] = {};
    const int a_row = warp_m + (lane & 15);
    const int a_col = (lane >> 4) * 8;
    const int b_row = warp_n + (lane & 7) + ((lane >> 4) << 3);
    const int b_col = ((lane >> 3) & 1) * 8;

    for (int ks = 0; ks < NK; ks++) {
        CP_WAIT1();
        __syncthreads();
        const int pf = ks + NSTG - 1;
        if (pf < NK) load_stage(pf, pf % NSTG);
        CP_COMMIT();
        const int buf = ks % NSTG;
        const uint32_t abase = sb + buf * STGB;
        const uint32_t bbase = abase + BM * ROWB;
        #pragma unroll
        for (int kk = 0; kk < 4; kk++) {
            uint32_t af[2][4], bfr[4][4];
            #pragma unroll
            for (int im = 0; im < 2; im++)
                ldm4(af[im][0], af[im][1], af[im][2], af[im][3],
                     abase + (a_row + im * 16) * ROWB + (kk * 16 + a_col) * 2);
            #pragma unroll
            for (int jn = 0; jn < 4; jn++)
                ldm4(bfr[jn][0], bfr[jn][1], bfr[jn][2], bfr[jn][3],
                     bbase + (b_row + jn * 16) * ROWB + (kk * 16 + b_col) * 2);
            #pragma unroll
            for (int jn = 0; jn < 4; jn++)
                #pragma unroll
                for (int im = 0; im < 2; im++) {
                    mma16816(acc[im][jn * 2 + 0], af[im], bfr[jn][0], bfr[jn][1]);
                    mma16816(acc[im][jn * 2 + 1], af[im], bfr[jn][2], bfr[jn][3]);
                }
        }
    }

    const int mb = m0 + warp_m + (lane >> 2);
    #pragma unroll
    for (int im = 0; im < 2; im++) {
        #pragma unroll
        for (int j = 0; j < 8; j++) {
            const int col = n0 + warp_n + j * 8 + (lane & 3) * 2;
            #pragma unroll
            for (int half = 0; half < 2; half++) {
                const int m = mb + im * 16 + half * 8;
                float v0 = acc[im][j][half * 2 + 0] + bias[col];
                float v1 = acc[im][j][half * 2 + 1] + bias[col + 1];
                if (MODE == 0) {
                    const int sct = col >> 9, h = (col >> 6) & 7, d = col & 63;
                    const int bi = m >> 8, nt = m & 255;
                    if (sct == 2) {
                        float2* dp = (float2*)(g_v +
                            (((size_t)(bi * NH + h) * NT + nt) * HDIM + d));
                        *dp = make_float2(v0, v1);
                    } else {
                        if (sct == 0) { v0 *= 0.125f; v1 *= 0.125f; }
                        __nv_bfloat16 h0, l0, h1, l1;
                        split1(v0, h0, l0); split1(v1, h1, l1);
                        __nv_bfloat16* base = ((sct == 0) ? g_qe : g_ke) +
                            ((size_t)(bi * NH + h) * NT + nt) * 128 + d;
                        __nv_bfloat162 th, tl;
                        th.x = h0; th.y = h1; tl.x = l0; tl.y = l1;
                        *(__nv_bfloat162*)(base)      = th;
                        *(__nv_bfloat162*)(base + 64) = tl;
                    }
                } else {
                    *(float2*)(outp + (size_t)m * MODEL + col) = make_float2(v0, v1);
                }
            }
        }
    }
}

// ---------------- s_mma: load-once, 3 term sweeps ---------------------------
#define SROW2 272u                       // 128 elems = 256B + 16B pad
#define SSMEM2 (2u * 128u * SROW2)       // 69632B

__global__ __launch_bounds__(256, 2) void s_mma()
{
    extern __shared__ char smem[];
    const uint32_t sb = smem_u32(smem);
    const int tid = threadIdx.x, wid = tid >> 5, lane = tid & 31;
    const int bh = blockIdx.y;
    const int m0 = (blockIdx.x >> 1) * 128;
    const int n0 = (blockIdx.x & 1) * 128;
    const __nv_bfloat16* gA = g_qe + (size_t)bh * NT * 128;
    const __nv_bfloat16* gB = g_ke + (size_t)bh * NT * 128;
    const int warp_m = (wid & 3) * 32;
    const int warp_n = (wid >> 2) * 64;
    const uint32_t abase = sb;
    const uint32_t bbase = sb + 128u * SROW2;

    #pragma unroll
    for (int t = 0; t < 16; t++) {
        const int idx = tid + t * 256;
        if (idx < 2048) {
            const int r = idx >> 4, cc = idx & 15;
            cp16(abase + r * SROW2 + cc * 16, gA + (size_t)(m0 + r) * 128 + cc * 8);
        } else {
            const int j = idx - 2048;
            const int r = j >> 4, cc = j & 15;
            cp16(bbase + r * SROW2 + cc * 16, gB + (size_t)(n0 + r) * 128 + cc * 8);
        }
    }
    CP_COMMIT();
    CP_WAIT0();
    __syncthreads();

    float acc[2][8][4] = {};
    const int a_row = warp_m + (lane & 15);
    const int a_col = (lane >> 4) * 8;
    const int b_row = warp_n + (lane & 7) + ((lane >> 4) << 3);
    const int b_col = ((lane >> 3) & 1) * 8;

    #pragma unroll
    for (int term = 0; term < 3; term++) {
        const int ao = (term == 1) ? 64 : 0;
        const int bo = (term == 2) ? 64 : 0;
        #pragma unroll
        for (int kk = 0; kk < 4; kk++) {
            uint32_t af[2][4], bfr[4][4];
            #pragma unroll
            for (int im = 0; im < 2; im++)
                ldm4(af[im][0], af[im][1], af[im][2], af[im][3],
                     abase + (a_row + im * 16) * SROW2 + (ao + kk * 16 + a_col) * 2);
            #pragma unroll
            for (int jn = 0; jn < 4; jn++)
                ldm4(bfr[jn][0], bfr[jn][1], bfr[jn][2], bfr[jn][3],
                     bbase + (b_row + jn * 16) * SROW2 + (bo + kk * 16 + b_col) * 2);
            #pragma unroll
            for (int jn = 0; jn < 4; jn++)
                #pragma unroll
                for (int im = 0; im < 2; im++) {
                    mma16816(acc[im][jn * 2 + 0], af[im], bfr[jn][0], bfr[jn][1]);
                    mma16816(acc[im][jn * 2 + 1], af[im], bfr[jn][2], bfr[jn][3]);
                }
        }
    }

    float* Sp = g_S + (size_t)bh * NT * NT;
    const int mb = m0 + warp_m + (lane >> 2);
    #pragma unroll
    for (int im = 0; im < 2; im++) {
        #pragma unroll
        for (int j = 0; j < 8; j++) {
            const int col = n0 + warp_n + j * 8 + (lane & 3) * 2;
            #pragma unroll
            for (int half = 0; half < 2; half++) {
                const int m = mb + im * 16 + half * 8;
                *(float2*)(Sp + (size_t)m * NT + col) =
                    make_float2(acc[im][j][half * 2], acc[im][j][half * 2 + 1]);
            }
        }
    }
}

// ---------------- vt_kernel: transpose + split V ----------------------------
__global__ __launch_bounds__(256) void vt_kernel()
{
    __shared__ float sv[128 * 65];
    const int bh = blockIdx.x, tid = threadIdx.x;
    const float* V = g_v + (size_t)bh * NT * HDIM;
    __nv_bfloat16* dst = g_vt + (size_t)bh * 64 * 512;
    for (int pass = 0; pass < 2; pass++) {
        const int kbase = pass * 128;
        for (int i = tid; i < 128 * 64; i += 256) {
            int k2 = i >> 6, n = i & 63;
            sv[k2 * 65 + n] = V[(size_t)(kbase + k2) * 64 + n];
        }
        __syncthreads();
        const int n = tid >> 2, q = tid & 3;
        for (int kk = 0; kk < 32; kk += 2) {
            const int k2 = q * 32 + kk;
            float v0 = sv[k2 * 65 + n], v1 = sv[(k2 + 1) * 65 + n];
            __nv_bfloat16 h0, l0, h1, l1;
            split1(v0, h0, l0); split1(v1, h1, l1);
            __nv_bfloat162 th, tl;
            th.x = h0; th.y = h1; tl.x = l0; tl.y = l1;
            const int k = kbase + k2;
            *(__nv_bfloat162*)(dst + (size_t)n * 512 + k)       = th;
            *(__nv_bfloat162*)(dst + (size_t)n * 512 + 256 + k) = tl;
        }
        __syncthreads();
    }
}

// ---------------- fused conv + softmax + AV ---------------------------------
// CTA = (128-row half, bh). smem: P chunk (32 x 1040B) + V_ext (64 x 1040B).
#define PROW 1040u
#define F_P  0u
#define F_V  (32u * PROW)                // 33280
#define FSMEM (F_V + 64u * PROW)         // 99840

__global__ __launch_bounds__(256, 2) void fused_sm_av(
    const float* __restrict__ pe_w, const float* __restrict__ pe_b,
    const float* __restrict__ rpb)
{
    extern __shared__ char smem[];
    const uint32_t sb = smem_u32(smem);
    const int tid = threadIdx.x, wid = tid >> 5, lane = tid & 31;
    const int bh = blockIdx.y;
    const int h  = bh & 7;
    const int m0 = blockIdx.x * 128;
    const float* S = g_S + (size_t)bh * NT * NT;
    const __nv_bfloat16* gV = g_vt + (size_t)bh * 64 * 512;

    // issue V_ext load (64 rows x 64 chunks of 16B)
    #pragma unroll
    for (int t = 0; t < 16; t++) {
        const int idx = tid + t * 256;
        const int r = idx >> 6, cc = idx & 63;
        cp16(sb + F_V + r * PROW + cc * 16, gV + (size_t)r * 512 + cc * 8);
    }
    CP_COMMIT();

    const int j = tid;                    // column owned in conv phase
    float w[15];
    #pragma unroll
    for (int t = 0; t < 15; t++) w[t] = pe_w[h * 15 + t];
    const float pb = pe_b[h];
    const int rj = j >> 4, cj = j & 15;

    float win[46];
    const int warp_m = (wid & 1) * 16;
    const int warp_n = (wid >> 1) * 16;
    const int a_row = warp_m + (lane & 15);
    const int a_col = (lane >> 4) * 8;
    const int b_row = warp_n + (lane & 7) + ((lane >> 4) << 3);
    const int b_col = ((lane >> 3) & 1) * 8;
    const int bi = bh >> 3, hh = bh & 7;

    for (int c = 0; c < 4; c++) {
        const int i0c = m0 + c * 32;
        // --- load / shift sliding window ---
        if (c == 0) {
            #pragma unroll
            for (int r = 0; r < 46; r++) {
                const int g = i0c - 7 + r;
                win[r] = (g >= 0 && g < NT) ? S[(size_t)g * NT + j] : 0.f;
            }
        } else {
            #pragma unroll
            for (int r = 0; r < 14; r++) win[r] = win[r + 32];
            #pragma unroll
            for (int r = 14; r < 46; r++) {
                const int g = i0c - 7 + r;
                win[r] = (g < NT) ? S[(size_t)g * NT + j] : 0.f;
            }
        }
        // --- conv: write fp32 logits into P buffer ---
        #pragma unroll
        for (int li = 0; li < 32; li++) {
            float conv = 0.f;
            #pragma unroll
            for (int t = 0; t < 15; t++)
                conv = fmaf(win[li + t], w[t], conv);
            const int ii = i0c + li;
            const int ri = ii >> 4, ci = ii & 15;
            const int idx = (ri - rj + 15) * 31 + (ci - cj + 15);
            *(float*)(smem + F_P + li * PROW + j * 4) =
                win[li + 7] + conv + pb + __ldg(&rpb[idx * 8 + h]);
        }
        if (c == 0) CP_WAIT0();
        __syncthreads();
        // --- softmax: warp per 4 rows, overwrite with split bf16 ---
        #pragma unroll
        for (int rr = 0; rr < 4; rr++) {
            const int lr = wid * 4 + rr;
            float vals[8];
            #pragma unroll
            for (int e = 0; e < 8; e++)
                vals[e] = *(const float*)(smem + F_P + lr * PROW + (lane + e * 32) * 4);
            float mx = vals[0];
            #pragma unroll
            for (int e = 1; e < 8; e++) mx = fmaxf(mx, vals[e]);
            #pragma unroll
            for (int o = 16; o; o >>= 1) mx = fmaxf(mx, __shfl_xor_sync(0xffffffffu, mx, o));
            float sum = 0.f;
            #pragma unroll
            for (int e = 0; e < 8; e++) { vals[e] = expf(vals[e] - mx); sum += vals[e]; }
            #pragma unroll
            for (int o = 16; o; o >>= 1) sum += __shfl_xor_sync(0xffffffffu, sum, o);
            const float inv = 1.f / sum;
            __nv_bfloat16* prow = (__nv_bfloat16*)(smem + F_P + lr * PROW);
            #pragma unroll
            for (int e = 0; e < 8; e++) {
                const int jj = lane + e * 32;
                __nv_bfloat16 hh2, ll2;
                split1(vals[e] * inv, hh2, ll2);
                prow[jj]       = hh2;
                prow[256 + jj] = ll2;
            }
        }
        __syncthreads();
        // --- mma: O_chunk = P_ext @ V_ext^T (3 terms) ---
        float acc[2][4] = {};
        #pragma unroll
        for (int term = 0; term < 3; term++) {
            const int ao = (term == 1) ? 256 : 0;
            const int bo = (term == 2) ? 256 : 0;
            #pragma unroll
            for (int ks = 0; ks < 16; ks++) {
                uint32_t a0, a1, a2, a3, b0, b1, b2, b3;
                ldm4(a0, a1, a2, a3,
                     sb + F_P + a_row * PROW + (ao + ks * 16 + a_col) * 2);
                ldm4(b0, b1, b2, b3,
                     sb + F_V + b_row * PROW + (bo + ks * 16 + b_col) * 2);
                uint32_t af[4] = {a0, a1, a2, a3};
                mma16816(acc[0], af, b0, b1);
                mma16816(acc[1], af, b2, b3);
            }
        }
        // --- epilogue: write O chunk (3-seg split) ---
        #pragma unroll
        for (int jn = 0; jn < 2; jn++) {
            const int col = warp_n + jn * 8 + (lane & 3) * 2;
            #pragma unroll
            for (int half = 0; half < 2; half++) {
                const int m = i0c + warp_m + (lane >> 2) + half * 8;
                __nv_bfloat16 h0, l0, h1, l1;
                split1(acc[jn][half * 2 + 0], h0, l0);
                split1(acc[jn][half * 2 + 1], h1, l1);
                __nv_bfloat162 th, tl;
                th.x = h0; th.y = h1; tl.x = l0; tl.y = l1;
                __nv_bfloat16* base = g_ohs + (size_t)(bi * NT + m) * KX + hh * 64 + col;
                *(__nv_bfloat162*)(base)        = th;
                *(__nv_bfloat162*)(base + 512)  = tl;
                *(__nv_bfloat162*)(base + 1024) = th;
            }
        }
        __syncthreads();   // protect P buffer before next conv overwrite
    }
}

// ---------------------------------------------------------------------------
extern "C" void kernel_launch(void* const* d_in, const int* in_sizes, int n_in,
                              void* d_out, int out_size)
{
    (void)in_sizes; (void)n_in; (void)out_size;
    const float* x      = (const float*)d_in[0];
    const float* qkv_w  = (const float*)d_in[1];
    const float* qkv_b  = (const float*)d_in[2];
    const float* pe_w   = (const float*)d_in[3];
    const float* pe_b   = (const float*)d_in[4];
    const float* rpb    = (const float*)d_in[5];
    const float* proj_w = (const float*)d_in[6];
    const float* proj_b = (const float*)d_in[7];
    float* out = (float*)d_out;

    static bool attr_done = false;
    if (!attr_done) {
        cudaFuncSetAttribute(gemm_mma<0>, cudaFuncAttributeMaxDynamicSharedMemorySize, GSMEM);
        cudaFuncSetAttribute(gemm_mma<1>, cudaFuncAttributeMaxDynamicSharedMemorySize, GSMEM);
        cudaFuncSetAttribute(s_mma, cudaFuncAttributeMaxDynamicSharedMemorySize, SSMEM2);
        cudaFuncSetAttribute(fused_sm_av, cudaFuncAttributeMaxDynamicSharedMemorySize, FSMEM);
        attr_done = true;
    }

    __nv_bfloat16 *xs, *qws, *pws, *ohs;
    cudaGetSymbolAddress((void**)&xs,  g_xs);
    cudaGetSymbolAddress((void**)&qws, g_qws);
    cudaGetSymbolAddress((void**)&pws, g_pws);
    cudaGetSymbolAddress((void**)&ohs, g_ohs);

    split_a_kernel<<<(MTOT * MODEL / 2 + 255) / 256, 256>>>(x, xs, MTOT * MODEL / 2);
    split_b_kernel<<<(QKVN * MODEL / 2 + 255) / 256, 256>>>(qkv_w, qws, QKVN * MODEL / 2);
    split_b_kernel<<<(MODEL * MODEL / 2 + 255) / 256, 256>>>(proj_w, pws, MODEL * MODEL / 2);

    gemm_mma<0><<<dim3(QKVN / BN, MTOT / BM), 256, GSMEM>>>(xs, qws, qkv_b, nullptr);

    vt_kernel<<<NBH, 256>>>();
    s_mma<<<dim3(4, NBH), 256, SSMEM2>>>();
    fused_sm_av<<<dim3(2, NBH), 256, FSMEM>>>(pe_w, pe_b, rpb);

    gemm_mma<1><<<dim3(MODEL / BN, MTOT / BM), 256, GSMEM>>>(ohs, pws, proj_b, out);
}